// round 11
// baseline (speedup 1.0000x reference)
#include <cuda_runtime.h>
#include <math.h>

#define N_ATOMS  4096
#define NRBF     16
#define NHID     64

#define NCELL1   8                       // cells per axis (BOX/CUTOFF = 40/5)
#define NCELLS   (NCELL1*NCELL1*NCELL1)  // 512
#define ACC_CAP  128                     // accepted neighbors: mean ~33, max ~70
#define INV_CELL 0.2f                    // 1 / 5.0

// ---- scratch (no allocations allowed) ----
__device__ float4 g_pos_sorted[N_ATOMS + 32];  // cell-major sorted positions (+pad)
__device__ int    g_cell_start[NCELLS + 1];    // prefix offsets into g_pos_sorted
__device__ float  g_block_e[512];              // per-block energy partials
__device__ int    g_done;                      // last-block ticket (reset in build)

// 1/(2*eta^2), eta = 0.5*(5.0-0.5)/16 = 9/64 -> A = 2048/81
#define RBF_A        25.28395061728395f
#define PI_OVER_CUT  0.6283185307179586f       // pi / 5.0
#define CUT_SQ       25.0f

__device__ __forceinline__ int cell_coord(float x)
{
    return min(NCELL1 - 1, max(0, (int)(x * INV_CELL)));
}

// ============================================================
// Kernel 1: stable counting sort of positions by cell.
// 64 blocks x 256 threads, warp per cell. Pass 1 computes the
// cell's global base (#atoms in lower cells); pass 2 scatters
// positions in index order (deterministic).
// ============================================================
__global__ __launch_bounds__(256)
void build_kernel(const float* __restrict__ pos)
{
    __shared__ int s_ids[N_ATOMS];   // 16 KB

    const int tid  = threadIdx.x;
    const int warp = tid >> 5;
    const int lane = tid & 31;
    const unsigned FULL = 0xffffffffu;
    const unsigned lt   = (1u << lane) - 1u;

    if (blockIdx.x == 0 && tid == 0) {
        g_done = 0;                          // replay-safe ticket reset
        g_cell_start[NCELLS] = N_ATOMS;
    }

    for (int a = tid; a < N_ATOMS; a += 256) {
        float x = pos[3 * a], y = pos[3 * a + 1], z = pos[3 * a + 2];
        int cx = cell_coord(x), cy = cell_coord(y), cz = cell_coord(z);
        s_ids[a] = (cz * NCELL1 + cy) * NCELL1 + cx;
    }
    __syncthreads();

    const int cell = blockIdx.x * 8 + warp;

    // pass 1: base = #atoms with id < cell
    int base = 0;
    #pragma unroll 4
    for (int b = 0; b < N_ATOMS; b += 32)
        base += __popc(__ballot_sync(FULL, s_ids[b + lane] < cell));
    if (lane == 0) g_cell_start[cell] = base;

    // pass 2: stable scatter of this cell's atoms (index order)
    int wpos = base;
    #pragma unroll 4
    for (int b = 0; b < N_ATOMS; b += 32) {
        bool eq = (s_ids[b + lane] == cell);
        unsigned m = __ballot_sync(FULL, eq);
        if (eq) {
            int a   = b + lane;
            int dst = wpos + __popc(m & lt);
            g_pos_sorted[dst] = make_float4(pos[3 * a], pos[3 * a + 1],
                                            pos[3 * a + 2], 0.0f);
        }
        wpos += __popc(m);
    }
}

// ============================================================
__device__ __forceinline__ float silu_f(float a)
{
    return a / (1.0f + __expf(-a));
}

__device__ __forceinline__ void rbf_batch(float sq, const float* __restrict__ c,
                                          float* __restrict__ f)
{
    float d = sqrtf(sq);                          // sentinel sq=1e8 -> d=1e4
    float w = 0.5f + 0.5f * __cosf(d * PI_OVER_CUT);
    #pragma unroll
    for (int k = 0; k < NRBF; k++) {
        float tt = d - c[k];
        float g  = __expf(-RBF_A * tt * tt);      // sentinel -> underflow to 0
        f[k] = fmaf(w, g, f[k]);
    }
}

// ============================================================
// Kernel 2: warp per sorted atom. Candidates = 9 contiguous runs
// of g_pos_sorted (3 x-adjacent cells merge per (y,z) row).
// Coalesced filter -> compact -> dense RBF -> fused MLP (weights
// staged in shared) -> block partial -> last-block sum.
// 512 blocks x 256 threads.
// ============================================================
__global__ __launch_bounds__(256)
void gather_kernel(const float* __restrict__ centers,
                   const float* __restrict__ W1, const float* __restrict__ b1,
                   const float* __restrict__ W2, const float* __restrict__ b2,
                   const float* __restrict__ W3, const float* __restrict__ b3,
                   float* __restrict__ out)
{
    __shared__ float s_W2[NHID * NHID];     // 16 KB
    __shared__ float s_W1[NRBF * NHID];     //  4 KB
    __shared__ float s_acc[8][ACC_CAP];     //  4 KB accepted sq per warp
    __shared__ float s_h1[8][NHID];         //  2 KB
    __shared__ float s_e[8];
    __shared__ int   s_last;
    __shared__ float s_red[256];

    const int tid  = threadIdx.x;
    const int warp = tid >> 5;
    const int lane = tid & 31;
    const int i    = blockIdx.x * 8 + warp;    // sorted atom slot
    const unsigned FULL = 0xffffffffu;
    const unsigned lt   = (1u << lane) - 1u;

    // stage weights (once per block)
    for (int t = tid; t < NHID * NHID; t += 256) s_W2[t] = W2[t];
    for (int t = tid; t < NRBF * NHID; t += 256) s_W1[t] = W1[t];
    __syncthreads();

    const float4 pi = g_pos_sorted[i];         // broadcast, 1 line
    const int cx = cell_coord(pi.x);
    const int cy = cell_coord(pi.y);
    const int cz = cell_coord(pi.z);

    // ---- 9 candidate runs: lanes 0..8 own one (y,z) row each ----
    int rs = 0, rl = 0;
    if (lane < 9) {
        int dz = lane / 3 - 1, dy = lane % 3 - 1;
        int z = cz + dz, y = cy + dy;
        if (z >= 0 && z < NCELL1 && y >= 0 && y < NCELL1) {
            int rowbase = (z * NCELL1 + y) * NCELL1;
            int x0 = max(0, cx - 1), x1 = min(NCELL1 - 1, cx + 1);
            rs = g_cell_start[rowbase + x0];
            rl = g_cell_start[rowbase + x1 + 1] - rs;
        }
    }

    // ---- filter pass over runs (coalesced LDG), compact accepted sq ----
    int acc = 0;
    #pragma unroll
    for (int r = 0; r < 9; r++) {
        int rs_b = __shfl_sync(FULL, rs, r);
        int rl_b = __shfl_sync(FULL, rl, r);
        for (int b = 0; b < rl_b; b += 32) {
            int k = b + lane;
            float4 pj = (k < rl_b) ? g_pos_sorted[rs_b + k]
                                   : make_float4(pi.x, pi.y, pi.z, 0.0f);
            float dx = pi.x - pj.x;
            float dy = pi.y - pj.y;
            float dzv = pi.z - pj.z;
            float sq = fmaf(dx, dx, fmaf(dy, dy, dzv * dzv));
            bool ok  = (sq > 0.0f) && (sq < CUT_SQ);   // excludes self exactly
            unsigned m = __ballot_sync(FULL, ok);
            if (ok) {
                int ofs = acc + __popc(m & lt);
                if (ofs < ACC_CAP) s_acc[warp][ofs] = sq;
            }
            acc += __popc(m);
        }
    }
    acc = min(acc, ACC_CAP);
    __syncwarp();

    // ---- dense RBF over accepted pairs (~1-2 batches) ----
    float c[NRBF];
    #pragma unroll
    for (int k = 0; k < NRBF; k++) c[k] = __ldg(&centers[k]);

    float f[NRBF];
    #pragma unroll
    for (int k = 0; k < NRBF; k++) f[k] = 0.0f;
    for (int b = 0; b < acc; b += 32) {
        float sqv = (b + lane < acc) ? s_acc[warp][b + lane] : 1e8f;
        rbf_batch(sqv, c, f);
    }

    // butterfly-reduce: every lane gets the full feature vector
    #pragma unroll
    for (int off = 16; off > 0; off >>= 1) {
        #pragma unroll
        for (int k = 0; k < NRBF; k++)
            f[k] += __shfl_xor_sync(FULL, f[k], off);
    }

    // ---- MLP, 2 hidden units per lane ----
    const int t0 = lane, t1 = lane + 32;
    float a0 = __ldg(&b1[t0]);
    float a1 = __ldg(&b1[t1]);
    #pragma unroll
    for (int k = 0; k < NRBF; k++) {
        a0 = fmaf(f[k], s_W1[k * NHID + t0], a0);
        a1 = fmaf(f[k], s_W1[k * NHID + t1], a1);
    }
    s_h1[warp][t0] = silu_f(a0);
    s_h1[warp][t1] = silu_f(a1);
    __syncwarp();

    float a2 = __ldg(&b2[t0]);
    float a3 = __ldg(&b2[t1]);
    #pragma unroll
    for (int u = 0; u < NHID; u += 4) {
        float4 hv = *reinterpret_cast<const float4*>(&s_h1[warp][u]);
        a2 = fmaf(hv.x, s_W2[(u + 0) * NHID + t0], a2);
        a2 = fmaf(hv.y, s_W2[(u + 1) * NHID + t0], a2);
        a2 = fmaf(hv.z, s_W2[(u + 2) * NHID + t0], a2);
        a2 = fmaf(hv.w, s_W2[(u + 3) * NHID + t0], a2);
        a3 = fmaf(hv.x, s_W2[(u + 0) * NHID + t1], a3);
        a3 = fmaf(hv.y, s_W2[(u + 1) * NHID + t1], a3);
        a3 = fmaf(hv.z, s_W2[(u + 2) * NHID + t1], a3);
        a3 = fmaf(hv.w, s_W2[(u + 3) * NHID + t1], a3);
    }

    float v = silu_f(a2) * __ldg(&W3[t0]) + silu_f(a3) * __ldg(&W3[t1]);
    #pragma unroll
    for (int off = 16; off > 0; off >>= 1)
        v += __shfl_down_sync(FULL, v, off);
    if (lane == 0) s_e[warp] = v + __ldg(&b3[0]);
    __syncthreads();

    // ---- block partial + last-block deterministic reduction ----
    if (tid == 0) {
        float be = 0.0f;
        #pragma unroll
        for (int w = 0; w < 8; w++) be += s_e[w];   // fixed warp order
        g_block_e[blockIdx.x] = be;
        __threadfence();
        int t = atomicAdd(&g_done, 1);
        s_last = (t == gridDim.x - 1);
    }
    __syncthreads();

    if (s_last) {
        float v2 = g_block_e[tid] + g_block_e[tid + 256];  // fixed order
        s_red[tid] = v2;
        __syncthreads();
        #pragma unroll
        for (int s = 128; s > 0; s >>= 1) {
            if (tid < s) s_red[tid] += s_red[tid + s];
            __syncthreads();
        }
        if (tid == 0) out[0] = s_red[0];
    }
}

// ============================================================
extern "C" void kernel_launch(void* const* d_in, const int* in_sizes, int n_in,
                              void* d_out, int out_size)
{
    const float* pos     = (const float*)d_in[0];
    const float* centers = (const float*)d_in[1];
    const float* W1      = (const float*)d_in[2];
    const float* b1      = (const float*)d_in[3];
    const float* W2      = (const float*)d_in[4];
    const float* b2      = (const float*)d_in[5];
    const float* W3      = (const float*)d_in[6];
    const float* b3      = (const float*)d_in[7];

    build_kernel<<<NCELLS / 8, 256>>>(pos);
    gather_kernel<<<N_ATOMS / 8, 256>>>(centers, W1, b1, W2, b2, W3, b3,
                                        (float*)d_out);
}

// round 12
// speedup vs baseline: 1.1606x; 1.1606x over previous
#include <cuda_runtime.h>
#include <math.h>

#define N_ATOMS  4096
#define NRBF     16
#define NHID     64

#define NCELL1   8                       // cells per axis (BOX/CUTOFF = 40/5)
#define NCELLS   (NCELL1*NCELL1*NCELL1)  // 512
#define ACC_CAP  96                      // accepted per HALF-candidate-set (mean ~17)
#define INV_CELL 0.2f                    // 1 / 5.0
#define GBLK     1024                    // gather blocks (4 atoms each)

// ---- scratch (no allocations allowed) ----
__device__ float4 g_pos_sorted[N_ATOMS + 32];  // cell-major sorted positions (+pad)
__device__ int    g_cell_start[NCELLS + 1];    // prefix offsets into g_pos_sorted
__device__ float  g_block_e[GBLK];             // per-block energy partials
__device__ int    g_done;                      // last-block ticket (reset in build)

// 1/(2*eta^2), eta = 0.5*(5.0-0.5)/16 = 9/64 -> A = 2048/81
#define RBF_A        25.28395061728395f
#define PI_OVER_CUT  0.6283185307179586f       // pi / 5.0
#define CUT_SQ       25.0f

__device__ __forceinline__ int cell_coord(float x)
{
    return min(NCELL1 - 1, max(0, (int)(x * INV_CELL)));
}

// ============================================================
// Kernel 1: stable counting sort of positions by cell.
// 128 blocks x 256 threads, TWO warps per cell (parity p scans
// atom half [p*2048, p*2048+2048)). Halves the serial ballot
// chain vs one warp/cell. Deterministic (index order preserved:
// half0 indices < half1 indices).
// ============================================================
__global__ __launch_bounds__(256)
void build_kernel(const float* __restrict__ pos)
{
    __shared__ int s_ids[N_ATOMS];   // 16 KB
    __shared__ int s_lt[8], s_eq[8];

    const int tid  = threadIdx.x;
    const int warp = tid >> 5;
    const int lane = tid & 31;
    const unsigned FULL = 0xffffffffu;
    const unsigned ltm  = (1u << lane) - 1u;

    if (blockIdx.x == 0 && tid == 0) {
        g_done = 0;                          // replay-safe ticket reset
        g_cell_start[NCELLS] = N_ATOMS;
    }

    for (int a = tid; a < N_ATOMS; a += 256) {
        float x = pos[3 * a], y = pos[3 * a + 1], z = pos[3 * a + 2];
        s_ids[a] = (cell_coord(z) * NCELL1 + cell_coord(y)) * NCELL1 + cell_coord(x);
    }
    __syncthreads();

    const int cell = blockIdx.x * 4 + (warp >> 1);
    const int p    = warp & 1;
    const int h0   = p * (N_ATOMS / 2);

    // pass 1 over own half: counts of (id < cell) and (id == cell)
    int lt_cnt = 0, eq_cnt = 0;
    #pragma unroll 4
    for (int b = 0; b < N_ATOMS / 2; b += 32) {
        int id = s_ids[h0 + b + lane];
        lt_cnt += __popc(__ballot_sync(FULL, id < cell));
        eq_cnt += __popc(__ballot_sync(FULL, id == cell));
    }
    if (lane == 0) { s_lt[warp] = lt_cnt; s_eq[warp] = eq_cnt; }
    __syncthreads();

    const int base  = s_lt[warp] + s_lt[warp ^ 1];          // atoms with id < cell (all)
    const int start = base + (p ? s_eq[warp - 1] : 0);      // stable: half0 first
    if (p == 0 && lane == 0) g_cell_start[cell] = base;

    // pass 2: stable scatter of own half's matching atoms
    int wpos = start;
    #pragma unroll 4
    for (int b = 0; b < N_ATOMS / 2; b += 32) {
        int  a  = h0 + b + lane;
        bool eq = (s_ids[a] == cell);
        unsigned m = __ballot_sync(FULL, eq);
        if (eq) {
            int dst = wpos + __popc(m & ltm);
            g_pos_sorted[dst] = make_float4(pos[3 * a], pos[3 * a + 1],
                                            pos[3 * a + 2], 0.0f);
        }
        wpos += __popc(m);
    }
}

// ============================================================
__device__ __forceinline__ float silu_f(float a)
{
    return a / (1.0f + __expf(-a));
}

__device__ __forceinline__ void rbf_batch(float sq, const float* __restrict__ c,
                                          float* __restrict__ f)
{
    float d = sqrtf(sq);                          // sentinel sq=1e8 -> d=1e4
    float w = 0.5f + 0.5f * __cosf(d * PI_OVER_CUT);
    #pragma unroll
    for (int k = 0; k < NRBF; k++) {
        float tt = d - c[k];
        float g  = __expf(-RBF_A * tt * tt);      // sentinel -> underflow to 0
        f[k] = fmaf(w, g, f[k]);
    }
}

// ============================================================
// Kernel 2: TWO WARPS PER ATOM (parity splits the 9 candidate
// runs). 1024 blocks x 256 threads = 8192 warps -> ~86% occ cap.
// Filter (coalesced runs) -> compact -> dense RBF -> pair-combine
// feats -> fused MLP (1 hidden unit/lane, __ldg weights) ->
// block partial -> last-block sum.
// ============================================================
__global__ __launch_bounds__(256)
void gather_kernel(const float* __restrict__ centers,
                   const float* __restrict__ W1, const float* __restrict__ b1,
                   const float* __restrict__ W2, const float* __restrict__ b2,
                   const float* __restrict__ W3, const float* __restrict__ b3,
                   float* __restrict__ out)
{
    __shared__ float s_acc[8][ACC_CAP];                 // 3 KB accepted sq per warp
    __shared__ __align__(16) float s_feat[4][2][NRBF];  // 512 B half-features
    __shared__ __align__(16) float s_h1[4][NHID];       // 1 KB hidden activations
    __shared__ float s_ev[4][2];
    __shared__ float s_e[4];
    __shared__ int   s_last;
    __shared__ float s_red[256];

    const int tid   = threadIdx.x;
    const int warp  = tid >> 5;
    const int lane  = tid & 31;
    const int a_loc = warp >> 1;              // 0..3  (atom within block)
    const int p     = warp & 1;               // candidate-half parity
    const int i     = blockIdx.x * 4 + a_loc; // sorted atom slot
    const unsigned FULL = 0xffffffffu;
    const unsigned ltm  = (1u << lane) - 1u;

    const float4 pi = g_pos_sorted[i];        // broadcast, 1 line
    const int cx = cell_coord(pi.x);
    const int cy = cell_coord(pi.y);
    const int cz = cell_coord(pi.z);

    // ---- 9 candidate runs: lanes 0..8 own one (y,z) row each ----
    int rs = 0, rl = 0;
    if (lane < 9) {
        int dz = lane / 3 - 1, dy = lane % 3 - 1;
        int z = cz + dz, y = cy + dy;
        if (z >= 0 && z < NCELL1 && y >= 0 && y < NCELL1) {
            int rowbase = (z * NCELL1 + y) * NCELL1;
            int x0 = max(0, cx - 1), x1 = min(NCELL1 - 1, cx + 1);
            rs = g_cell_start[rowbase + x0];
            rl = g_cell_start[rowbase + x1 + 1] - rs;
        }
    }

    // ---- filter my half of the runs (p=0: 0..4, p=1: 5..8) ----
    const int r0 = p ? 5 : 0;
    const int r1 = p ? 9 : 5;
    int acc = 0;
    for (int r = r0; r < r1; r++) {
        int rs_b = __shfl_sync(FULL, rs, r);
        int rl_b = __shfl_sync(FULL, rl, r);
        for (int b = 0; b < rl_b; b += 32) {
            int k = b + lane;
            float4 pj = (k < rl_b) ? g_pos_sorted[rs_b + k]
                                   : make_float4(pi.x, pi.y, pi.z, 0.0f);
            float dx  = pi.x - pj.x;
            float dy  = pi.y - pj.y;
            float dzv = pi.z - pj.z;
            float sq  = fmaf(dx, dx, fmaf(dy, dy, dzv * dzv));
            bool  ok  = (sq > 0.0f) && (sq < CUT_SQ);   // excludes self exactly
            unsigned m = __ballot_sync(FULL, ok);
            if (ok) {
                int ofs = acc + __popc(m & ltm);
                if (ofs < ACC_CAP) s_acc[warp][ofs] = sq;
            }
            acc += __popc(m);
        }
    }
    acc = min(acc, ACC_CAP);
    __syncwarp();

    // ---- dense RBF over accepted pairs (~1 batch per half) ----
    float c[NRBF];
    #pragma unroll
    for (int k = 0; k < NRBF; k++) c[k] = __ldg(&centers[k]);

    float f[NRBF];
    #pragma unroll
    for (int k = 0; k < NRBF; k++) f[k] = 0.0f;
    for (int b = 0; b < acc; b += 32) {
        float sqv = (b + lane < acc) ? s_acc[warp][b + lane] : 1e8f;
        rbf_batch(sqv, c, f);
    }

    // butterfly-reduce within warp
    #pragma unroll
    for (int off = 16; off > 0; off >>= 1) {
        #pragma unroll
        for (int k = 0; k < NRBF; k++)
            f[k] += __shfl_xor_sync(FULL, f[k], off);
    }

    // ---- combine the two half-feature vectors ----
    if (lane < NRBF) s_feat[a_loc][p][lane] = f[lane];
    __syncthreads();
    #pragma unroll
    for (int k = 0; k < NRBF; k++)
        f[k] += s_feat[a_loc][p ^ 1][k];      // every lane: full features

    // ---- MLP: 1 hidden unit per lane (unit t = p*32 + lane) ----
    const int t = p * 32 + lane;
    float a0 = __ldg(&b1[t]);
    #pragma unroll
    for (int k = 0; k < NRBF; k++)
        a0 = fmaf(f[k], __ldg(&W1[k * NHID + t]), a0);
    s_h1[a_loc][t] = silu_f(a0);
    __syncthreads();

    float a2 = __ldg(&b2[t]);
    #pragma unroll
    for (int u = 0; u < NHID; u += 4) {
        float4 hv = *reinterpret_cast<const float4*>(&s_h1[a_loc][u]);
        a2 = fmaf(hv.x, __ldg(&W2[(u + 0) * NHID + t]), a2);
        a2 = fmaf(hv.y, __ldg(&W2[(u + 1) * NHID + t]), a2);
        a2 = fmaf(hv.z, __ldg(&W2[(u + 2) * NHID + t]), a2);
        a2 = fmaf(hv.w, __ldg(&W2[(u + 3) * NHID + t]), a2);
    }

    float v = silu_f(a2) * __ldg(&W3[t]);
    #pragma unroll
    for (int off = 16; off > 0; off >>= 1)
        v += __shfl_down_sync(FULL, v, off);
    if (lane == 0) s_ev[a_loc][p] = v;
    __syncthreads();

    if (p == 0 && lane == 0)
        s_e[a_loc] = s_ev[a_loc][0] + s_ev[a_loc][1] + __ldg(&b3[0]);
    __syncthreads();

    // ---- block partial + last-block deterministic reduction ----
    if (tid == 0) {
        float be = s_e[0] + s_e[1] + s_e[2] + s_e[3];   // fixed order
        g_block_e[blockIdx.x] = be;
        __threadfence();
        int tk = atomicAdd(&g_done, 1);
        s_last = (tk == gridDim.x - 1);
    }
    __syncthreads();

    if (s_last) {
        float v2 = g_block_e[tid]       + g_block_e[tid + 256]
                 + g_block_e[tid + 512] + g_block_e[tid + 768];  // fixed order
        s_red[tid] = v2;
        __syncthreads();
        #pragma unroll
        for (int s = 128; s > 0; s >>= 1) {
            if (tid < s) s_red[tid] += s_red[tid + s];
            __syncthreads();
        }
        if (tid == 0) out[0] = s_red[0];
    }
}

// ============================================================
extern "C" void kernel_launch(void* const* d_in, const int* in_sizes, int n_in,
                              void* d_out, int out_size)
{
    const float* pos     = (const float*)d_in[0];
    const float* centers = (const float*)d_in[1];
    const float* W1      = (const float*)d_in[2];
    const float* b1      = (const float*)d_in[3];
    const float* W2      = (const float*)d_in[4];
    const float* b2      = (const float*)d_in[5];
    const float* W3      = (const float*)d_in[6];
    const float* b3      = (const float*)d_in[7];

    build_kernel<<<NCELLS / 4, 256>>>(pos);
    gather_kernel<<<GBLK, 256>>>(centers, W1, b1, W2, b2, W3, b3,
                                 (float*)d_out);
}